// round 17
// baseline (speedup 1.0000x reference)
#include <cuda_runtime.h>
#include <cuda_bf16.h>
#include <math.h>
#include <float.h>

// Shapes (fixed): B=4, NP=4096, D_FEAT=8, N=16, DM=16, DO=8, NM=64, PNM=64
#define BIGF 99999999.0f

// ---------------- scratch (__device__ globals) ----------------------------
__device__ int   g_idx[4 * 4096 * 16];      // knn indices, ascending-distance order
__device__ float g_zpart[4 * 4096 * 64];    // per-(b,n) z partial sums
__device__ float g_zp2[4 * 128 * 64];       // stage-1 z reduction partials
__device__ float g_zm[4 * 8];               // z @ Wmz + bmz
__device__ float g_zv[4 * 64];              // z @ Wvz + bvz
__device__ int   g_ctr;                     // zred completion counter (self-resetting)

#define CE(a, b) { float _mn = fminf(a, b); b = fmaxf(a, b); a = _mn; }

__device__ __forceinline__ unsigned long long pack2(float a, float b) {
    unsigned long long r;
    asm("mov.b64 %0, {%1, %2};" : "=l"(r) : "f"(a), "f"(b));
    return r;
}
__device__ __forceinline__ void unpack2(unsigned long long v, float& a, float& b) {
    asm("mov.b64 {%0, %1}, %2;" : "=f"(a), "=f"(b) : "l"(v));
}
__device__ __forceinline__ void ffma2(unsigned long long& acc,
                                      unsigned long long ab, unsigned long long cd) {
    asm("fma.rn.f32x2 %0, %1, %2, %0;" : "+l"(acc) : "l"(ab), "l"(cd));
}

// ---------------- kNN: persistent, 2 queries/warp, batched bitonic --------
// (R14/R15 selection path — bit-identical output; pinned.)
#define KNN_SMEM (4096*16*2 + 4096*4)   // xs0, xs1, n2h = 147456 B
#define KNN_BLOCKS 148

__global__ __launch_bounds__(1024, 1) void knn_kernel(
    const float* __restrict__ x,
    const float* __restrict__ z,
    const float* __restrict__ Wmz, const float* __restrict__ bmz,
    const float* __restrict__ Wvz, const float* __restrict__ bvz)
{
    extern __shared__ char smem_raw[];
    float4* xs0 = (float4*)smem_raw;                        // [4096]
    float4* xs1 = (float4*)(smem_raw + 4096 * 16);          // [4096]
    float*  n2h = (float*) (smem_raw + 4096 * 32);          // [4096] = n2/2

    int b = blockIdx.x & 3;
    int r = blockIdx.x >> 2;               // 0..36
    // contiguous query range: 4096 = 37*110 + 26 -> first 26 ranges get 111
    int qbase = r * 110 + (r < 26 ? r : 26);
    int qcnt  = 110 + (r < 26 ? 1 : 0);
    int npair = (qcnt + 1) >> 1;

    int tid  = threadIdx.x;
    int w    = tid >> 5;
    int lane = tid & 31;

    const float* xb = x + (b << 15);

    // stage points + exact n2 (mul + serial rn adds), stored halved
    #pragma unroll
    for (int k = 0; k < 4; k++) {
        int p = tid + (k << 10);
        float4 a = *(const float4*)(xb + p * 8);
        float4 c = *(const float4*)(xb + p * 8 + 4);
        xs0[p] = a;
        xs1[p] = c;
        float s = __fmul_rn(a.x, a.x);
        s = __fadd_rn(s, __fmul_rn(a.y, a.y));
        s = __fadd_rn(s, __fmul_rn(a.z, a.z));
        s = __fadd_rn(s, __fmul_rn(a.w, a.w));
        s = __fadd_rn(s, __fmul_rn(c.x, c.x));
        s = __fadd_rn(s, __fmul_rn(c.y, c.y));
        s = __fadd_rn(s, __fmul_rn(c.z, c.z));
        s = __fadd_rn(s, __fmul_rn(c.w, c.w));
        n2h[p] = 0.5f * s;                 // lossless halving
    }
    __syncthreads();

    // ---- folded zmix (block r==36 of each batch; bit-identical math) ----
    if (r == 36) {
        if (tid < 64) {                    // zv: this batch's 64 outputs
            int j = tid;
            float s = bvz[j];
            #pragma unroll 8
            for (int p = 0; p < 64; p++) s = fmaf(z[b * 64 + p], Wvz[p * 64 + j], s);
            g_zv[b * 64 + j] = s;
        } else if (tid < 72) {             // zm: this batch's 8 outputs
            int j = tid - 64;
            float s = bmz[j];
            #pragma unroll 8
            for (int p = 0; p < 64; p++) s = fmaf(z[b * 64 + p], Wmz[p * 8 + j], s);
            g_zm[b * 8 + j] = s;
        }
    }

    // warp-level query-pair loop (guard warp-uniform; shuffles full-mask)
    for (int qp = w; qp < npair; qp += 32) {
        int iA = qbase + 2 * qp;
        int iB = (2 * qp + 1 < qcnt) ? (iA + 1) : iA;
        float4 aA0 = xs0[iA], aA1 = xs1[iA];
        float4 aB0 = xs0[iB], aB1 = xs1[iB];

        // ---- single pass: per-lane top-8 of e-keys for both queries ----
        float A0 = FLT_MAX, A1 = FLT_MAX, A2 = FLT_MAX, A3 = FLT_MAX,
              A4 = FLT_MAX, A5 = FLT_MAX, A6 = FLT_MAX, A7 = FLT_MAX;
        float B0 = FLT_MAX, B1 = FLT_MAX, B2 = FLT_MAX, B3 = FLT_MAX,
              B4 = FLT_MAX, B5 = FLT_MAX, B6 = FLT_MAX, B7 = FLT_MAX;
        {
            int j = lane;
            #pragma unroll 1
            for (int kb = 0; kb < 32; kb++) {
                float bkA[4], bkB[4];
                #pragma unroll
                for (int c4 = 0; c4 < 4; c4++) {
                    int jj = j + (c4 << 5);
                    float4 p0 = xs0[jj];
                    float4 p1 = xs1[jj];
                    float h  = n2h[jj];
                    float eA = h;
                    eA = fmaf(-aA0.x, p0.x, eA);
                    eA = fmaf(-aA0.y, p0.y, eA);
                    eA = fmaf(-aA0.z, p0.z, eA);
                    eA = fmaf(-aA0.w, p0.w, eA);
                    eA = fmaf(-aA1.x, p1.x, eA);
                    eA = fmaf(-aA1.y, p1.y, eA);
                    eA = fmaf(-aA1.z, p1.z, eA);
                    eA = fmaf(-aA1.w, p1.w, eA);
                    bkA[c4] = __uint_as_float(
                        (__float_as_uint(eA) & 0xFFFFF000u) | (unsigned)jj);
                    float eB = h;
                    eB = fmaf(-aB0.x, p0.x, eB);
                    eB = fmaf(-aB0.y, p0.y, eB);
                    eB = fmaf(-aB0.z, p0.z, eB);
                    eB = fmaf(-aB0.w, p0.w, eB);
                    eB = fmaf(-aB1.x, p1.x, eB);
                    eB = fmaf(-aB1.y, p1.y, eB);
                    eB = fmaf(-aB1.z, p1.z, eB);
                    eB = fmaf(-aB1.w, p1.w, eB);
                    bkB[c4] = __uint_as_float(
                        (__float_as_uint(eB) & 0xFFFFF000u) | (unsigned)jj);
                }
                // query A: sort4 + partial merge + clean
                CE(bkA[0], bkA[1]); CE(bkA[2], bkA[3]);
                CE(bkA[0], bkA[2]); CE(bkA[1], bkA[3]);
                CE(bkA[1], bkA[2]);
                A4 = fminf(A4, bkA[3]);
                A5 = fminf(A5, bkA[2]);
                A6 = fminf(A6, bkA[1]);
                A7 = fminf(A7, bkA[0]);
                CE(A0, A4); CE(A1, A5); CE(A2, A6); CE(A3, A7);
                CE(A0, A2); CE(A1, A3); CE(A4, A6); CE(A5, A7);
                CE(A0, A1); CE(A2, A3); CE(A4, A5); CE(A6, A7);
                // query B: sort4 + partial merge + clean
                CE(bkB[0], bkB[1]); CE(bkB[2], bkB[3]);
                CE(bkB[0], bkB[2]); CE(bkB[1], bkB[3]);
                CE(bkB[1], bkB[2]);
                B4 = fminf(B4, bkB[3]);
                B5 = fminf(B5, bkB[2]);
                B6 = fminf(B6, bkB[1]);
                B7 = fminf(B7, bkB[0]);
                CE(B0, B4); CE(B1, B5); CE(B2, B6); CE(B3, B7);
                CE(B0, B2); CE(B1, B3); CE(B4, B6); CE(B5, B7);
                CE(B0, B1); CE(B2, B3); CE(B4, B5); CE(B6, B7);
                j += 128;
            }
        }

        // ---- per query: 20-round tournament + exact re-rank ----
        #pragma unroll 1
        for (int qq = 0; qq < 2; qq++) {
            int i = qq ? iB : iA;
            float s0 = qq ? B0 : A0, s1 = qq ? B1 : A1,
                  s2 = qq ? B2 : A2, s3 = qq ? B3 : A3,
                  s4 = qq ? B4 : A4, s5 = qq ? B5 : A5,
                  s6 = qq ? B6 : A6, s7 = qq ? B7 : A7;

            float head = s0;
            float surv = FLT_MAX;
            #pragma unroll 1
            for (int round = 0; round < 20; round++) {
                float m = head;
                m = fminf(m, __shfl_xor_sync(0xffffffffu, m, 16));
                m = fminf(m, __shfl_xor_sync(0xffffffffu, m, 8));
                m = fminf(m, __shfl_xor_sync(0xffffffffu, m, 4));
                m = fminf(m, __shfl_xor_sync(0xffffffffu, m, 2));
                m = fminf(m, __shfl_xor_sync(0xffffffffu, m, 1));
                if (round == lane) surv = m;
                unsigned bal = __ballot_sync(0xffffffffu, head == m);
                int leader = __ffs(bal) - 1;
                if (lane == leader) {
                    s0 = s1; s1 = s2; s2 = s3; s3 = s4;
                    s4 = s5; s5 = s6; s6 = s7; s7 = FLT_MAX;
                    head = s0;
                }
            }

            bool valid = (lane < 20) && (surv != FLT_MAX);
            int j = (int)(__float_as_uint(surv) & 0xFFFu);
            unsigned long long pk = 0xffffffffffffffffull;
            if (valid) {
                float4 a0 = xs0[i], a1 = xs1[i];
                float4 p0 = xs0[j], p1 = xs1[j];
                // reference-exact: serial FMA dot, (n2i+n2j)-2*dot, sqrt
                float n2i = 2.0f * n2h[i];     // lossless
                float n2j = 2.0f * n2h[j];
                float dot = __fmul_rn(a0.x, p0.x);
                dot = __fmaf_rn(a0.y, p0.y, dot);
                dot = __fmaf_rn(a0.z, p0.z, dot);
                dot = __fmaf_rn(a0.w, p0.w, dot);
                dot = __fmaf_rn(a1.x, p1.x, dot);
                dot = __fmaf_rn(a1.y, p1.y, dot);
                dot = __fmaf_rn(a1.z, p1.z, dot);
                dot = __fmaf_rn(a1.w, p1.w, dot);
                float d2 = __fsub_rn(__fadd_rn(n2i, n2j), __fmul_rn(2.0f, dot));
                float dd = sqrtf(fmaxf(d2, 0.0f));
                if (dd == 0.0f || j == i) dd = BIGF;
                pk = ((unsigned long long)__float_as_uint(dd) << 32) | (unsigned)j;
            }
            int rank = 0;
            #pragma unroll
            for (int m = 0; m < 32; m++) {
                unsigned long long o = __shfl_sync(0xffffffffu, pk, m);
                rank += (o < pk) ? 1 : 0;
            }
            if (valid && rank < 16)
                g_idx[(b * 4096 + i) * 16 + rank] = j;
        }
    }
}

// ---------------- features + fused matmuls: block per (b,n) ---------------
// (R15 version — pinned.)
__global__ __launch_bounds__(128) void feat_kernel(
    const float* __restrict__ x,
    const float* __restrict__ Wm2, const float* __restrict__ bm2,
    const float* __restrict__ Wm3, const float* __restrict__ bm3,
    const float* __restrict__ Wv2, const float* __restrict__ bv2,
    const float* __restrict__ Wv3, const float* __restrict__ bv3,
    const float* __restrict__ Wmx, const float* __restrict__ bmx,
    const float* __restrict__ Wvx, const float* __restrict__ bvx,
    float* __restrict__ xout)
{
    int b = blockIdx.x >> 12;
    int n = blockIdx.x & 4095;
    int t = threadIdx.x;

    __shared__ __align__(16) float g[16][8];
    __shared__ __align__(16) float msm[15][32];
    __shared__ __align__(16) float vsm[15][32];
    __shared__ float mpart[8][8][15];   // [j][slice][r]
    __shared__ float xr[8][15];

    // gather 16 neighbor feature vectors
    {
        int s = t >> 3, d = t & 7;
        int nb = g_idx[(b * 4096 + n) * 16 + s] & 4095;
        g[s][d] = x[(size_t)(b * 4096 + nb) * 8 + d];
    }

    // feature-phase role
    int c   = t & 31;
    int mat = (t >> 5) & 1;
    int rh  = t >> 6;
    bool o3 = (c >= 16);
    int  k  = o3 ? (c - 16) : c;
    float w0, w1, w2 = 0.f, bb;
    if (!o3) {
        w0 = mat ? Wv2[k]      : Wm2[k];
        w1 = mat ? Wv2[16 + k] : Wm2[16 + k];
        bb = mat ? bv2[k]      : bm2[k];
    } else {
        w0 = mat ? Wv3[k]      : Wm3[k];
        w1 = mat ? Wv3[16 + k] : Wm3[16 + k];
        w2 = mat ? Wv3[32 + k] : Wm3[32 + k];
        bb = mat ? bv3[k]      : bm3[k];
    }
    __syncthreads();

    // r-invariant base: order2 p = g0*w0+b ; order3 p = g0*w0+g1*w1+b
    float p[8];
    #pragma unroll
    for (int d = 0; d < 8; d++) {
        float base = fmaf(g[0][d], w0, bb);
        p[d] = o3 ? fmaf(g[1][d], w1, base) : base;
    }
    float wlast = o3 ? w2 : w1;
    float* smo = mat ? &vsm[0][0] : &msm[0][0];

    int r0 = rh ? 8 : 0;
    int r1 = rh ? 15 : 8;
    for (int r = r0; r < r1; r++) {
        float ssum = 0.f;
        if (o3 && r == 14) {
            // tuple (0,2,3): g0*w0 + g2*w1 + g3*w2 + b
            #pragma unroll
            for (int d = 0; d < 8; d++) {
                float v = fmaf(g[3][d], w2,
                          fmaf(g[2][d], w1,
                          fmaf(g[0][d], w0, bb)));
                ssum += fmaxf(v, 0.f);
            }
        } else {
            int a = o3 ? (r + 2) : (r + 1);
            #pragma unroll
            for (int d = 0; d < 8; d++)
                ssum += fmaxf(fmaf(g[a][d], wlast, p[d]), 0.f);
        }
        smo[r * 32 + c] = ssum * 0.125f;   // mean over d (8)
    }
    __syncthreads();

    if (t < 64) {
        // v-matmul: output j=t, K=32, 15 tuples — packed f32x2 FMA
        unsigned long long acc2[15];
        #pragma unroll
        for (int r = 0; r < 15; r++) acc2[r] = 0ull;   // {0.f, 0.f}
        #pragma unroll
        for (int k4 = 0; k4 < 32; k4 += 4) {
            float q0 = Wvx[(k4 + 0) * 64 + t];
            float q1 = Wvx[(k4 + 1) * 64 + t];
            float q2 = Wvx[(k4 + 2) * 64 + t];
            float q3 = Wvx[(k4 + 3) * 64 + t];
            unsigned long long w01 = pack2(q0, q1);
            unsigned long long w23 = pack2(q2, q3);
            #pragma unroll
            for (int r = 0; r < 15; r++) {
                float4 vv = *(const float4*)&vsm[r][k4];
                ffma2(acc2[r], pack2(vv.x, vv.y), w01);
                ffma2(acc2[r], pack2(vv.z, vv.w), w23);
            }
        }
        float bias = bvx[t] + g_zv[b * 64 + t];
        float s = 0.f;
        #pragma unroll
        for (int r = 0; r < 15; r++) {
            float lo, hi;
            unpack2(acc2[r], lo, hi);
            s += fmaxf(__fadd_rn(lo, hi) + bias, 0.f);
        }
        g_zpart[(size_t)(b * 4096 + n) * 64 + t] = s;
    } else {
        // m-matmul: 8 outputs x 8 k-slices of 4
        int q = t - 64;
        int j = q >> 3;
        int sl = q & 7;
        int k0 = sl * 4;
        float q0 = Wmx[(k0 + 0) * 8 + j];
        float q1 = Wmx[(k0 + 1) * 8 + j];
        float q2 = Wmx[(k0 + 2) * 8 + j];
        float q3 = Wmx[(k0 + 3) * 8 + j];
        #pragma unroll
        for (int r = 0; r < 15; r++) {
            float4 mv = *(const float4*)&msm[r][k0];
            float a = mv.x * q0;
            a = fmaf(mv.y, q1, a);
            a = fmaf(mv.z, q2, a);
            a = fmaf(mv.w, q3, a);
            mpart[j][sl][r] = a;
        }
    }
    __syncthreads();

    if (t < 120) {
        int j = t / 15, r = t % 15;
        float s = 0.f;
        #pragma unroll
        for (int sl = 0; sl < 8; sl++) s += mpart[j][sl][r];
        xr[j][r] = fmaxf(s + bmx[j] + g_zm[b * 8 + j], 0.f);
    }
    __syncthreads();
    if (t < 8) {
        float s = 0.f;
        #pragma unroll
        for (int r = 0; r < 15; r++) s += xr[t][r];
        xout[(size_t)b * 32768 + n * 8 + t] = s * (1.f / 15.f);
    }
}

// ---------------- z reduction: single kernel, last-block stage 2 ----------
// 512 blocks; each reduces a 32-row chunk (R16 stage-1 math, unchanged) and
// publishes to g_zp2. The last block to finish (int counter; deterministic)
// performs stage 2 for all 4 batches with R16's exact summation order, then
// resets the counter for the next graph replay.
__global__ __launch_bounds__(256) void zred_kernel(float* __restrict__ out)
{
    int b = blockIdx.x >> 7;
    int c = blockIdx.x & 127;              // 32-row chunk
    int t = threadIdx.x;
    int q = t >> 6, j = t & 63;            // q: 8-row subchunk
    const float* zp = g_zpart + ((size_t)(b * 4096 + c * 32) * 64);
    float s = 0.f;
    #pragma unroll 8
    for (int k = q * 8; k < q * 8 + 8; k++) s += zp[k * 64 + j];
    __shared__ float red[256];
    __shared__ int is_last;
    red[t] = s;
    __syncthreads();
    if (t < 64)
        g_zp2[(b * 128 + c) * 64 + t] =
            red[t] + red[t + 64] + red[t + 128] + red[t + 192];

    // publish, then elect the last block
    __threadfence();
    __syncthreads();
    if (t == 0) {
        int prev = atomicAdd(&g_ctr, 1);
        is_last = (prev == 511) ? 1 : 0;
    }
    __syncthreads();
    if (!is_last) return;

    // ---- stage 2 (R16 zred2 math, all 4 batches) ----
    __threadfence();                       // acquire side
    for (int bb = 0; bb < 4; bb++) {
        float s2 = 0.f;
        #pragma unroll 8
        for (int cc = q * 32; cc < q * 32 + 32; cc++)
            s2 += g_zp2[(bb * 128 + cc) * 64 + j];
        __syncthreads();
        red[t] = s2;
        __syncthreads();
        if (t < 64)
            out[131072 + bb * 64 + t] =
                (red[t] + red[t + 64] + red[t + 128] + red[t + 192]) * (1.f / 61440.f);
    }
    if (t == 0) g_ctr = 0;                 // reset for next graph replay
}

// ---------------- launch ---------------------------------------------------
extern "C" void kernel_launch(void* const* d_in, const int* in_sizes, int n_in,
                              void* d_out, int out_size)
{
    const float* x   = (const float*)d_in[0];
    const float* z   = (const float*)d_in[1];
    const float* Wm2 = (const float*)d_in[2];
    const float* bm2 = (const float*)d_in[3];
    const float* Wm3 = (const float*)d_in[4];
    const float* bm3 = (const float*)d_in[5];
    const float* Wv2 = (const float*)d_in[6];
    const float* bv2 = (const float*)d_in[7];
    const float* Wv3 = (const float*)d_in[8];
    const float* bv3 = (const float*)d_in[9];
    const float* Wmx = (const float*)d_in[10];
    const float* bmx = (const float*)d_in[11];
    const float* Wvx = (const float*)d_in[12];
    const float* bvx = (const float*)d_in[13];
    const float* Wmz = (const float*)d_in[14];
    const float* bmz = (const float*)d_in[15];
    const float* Wvz = (const float*)d_in[16];
    const float* bvz = (const float*)d_in[17];
    float* out = (float*)d_out;

    cudaFuncSetAttribute(knn_kernel,
                         cudaFuncAttributeMaxDynamicSharedMemorySize, KNN_SMEM);

    knn_kernel<<<KNN_BLOCKS, 1024, KNN_SMEM>>>(x, z, Wmz, bmz, Wvz, bvz);
    feat_kernel<<<16384, 128>>>(x,
                                Wm2, bm2, Wm3, bm3, Wv2, bv2, Wv3, bv3,
                                Wmx, bmx, Wvx, bvx, out);
    zred_kernel<<<512, 256>>>(out);
}